// round 14
// baseline (speedup 1.0000x reference)
#include <cuda_runtime.h>

#define NG  8     // graphs
#define NN  128   // nodes
#define DIM 128   // embedding dim
#define NE  128   // edge types
#define VEC 300   // word-vec dim

// ---- scratch (device globals; no allocations allowed) ----
__device__ __align__(16) float g_vacc[NG][NN][DIM];
__device__ __align__(16) float g_bvec[NG][NN][DIM];
__device__ int   g_parent[NG][NN];
__device__ int   g_ccount[NG][NN];     // original child count (relu test)
__device__ int   g_ccount_eff[NG][NN]; // excl. path child (wait count)
__device__ int   g_cdone[NG][NN];
__device__ int   g_onpath[NG][NN];
__device__ int   g_pathidx[NG][NN];    // index along pos->root path
__device__ int   g_path[NG][NN];
__device__ int   g_plen[NG];
__device__ int   g_edges_eff[NN];
__device__ int   g_pflag[NG][NN];      // per-path-index completion flags
__device__ float g_dscoreg[NG];

// ---- acquire/release primitives ----
__device__ __forceinline__ int ld_acquire(const int* p) {
    int v;
    asm volatile("ld.acquire.gpu.global.u32 %0, [%1];" : "=r"(v) : "l"(p) : "memory");
    return v;
}
__device__ __forceinline__ void red_release_add(int* p, int v) {
    asm volatile("red.release.gpu.global.add.u32 [%0], %1;" :: "l"(p), "r"(v) : "memory");
}
// ALL lanes spin (hot, tree critical path).
__device__ __forceinline__ void wait_ge(const int* p, int need) {
    while (ld_acquire(p) < need) { }
    __syncwarp();
}
// Backoff poll (phase-2 gating, co-resident with tree warps).
__device__ __forceinline__ void wait_ge_bk(const int* p, int need) {
    while (ld_acquire(p) < need) { __nanosleep(64); }
    __syncwarp();
}

// ---------------------------------------------------------------------------
// Streaming matvec: thread owns 4 consecutive output dims (d0 = 4*lane).
// Double-buffered register chunks -> 2*CH LDG.128 in flight per thread.
// ---------------------------------------------------------------------------
template<int K, int CH>
__device__ __forceinline__ void mv_stream(const float4* __restrict__ W4,
                                          const float* __restrict__ r,
                                          float4& m) {
    constexpr int STEP = 2 * CH;
    constexpr int NCH  = (K + STEP - 1) / STEP;
    float4 A[CH], B[CH];
#pragma unroll
    for (int i = 0; i < CH; ++i)
        A[i] = (i < K) ? W4[i * (DIM / 4)] : make_float4(0.f, 0.f, 0.f, 0.f);
#pragma unroll
    for (int o = 0; o < NCH; ++o) {
        const int kb = o * STEP, k2 = kb + CH, k3 = kb + STEP;
#pragma unroll
        for (int i = 0; i < CH; ++i)
            B[i] = (k2 + i < K) ? W4[(k2 + i) * (DIM / 4)] : make_float4(0.f, 0.f, 0.f, 0.f);
#pragma unroll
        for (int i = 0; i < CH; ++i)
            if (kb + i < K) {
                const float rk = r[kb + i];
                m.x += rk * A[i].x; m.y += rk * A[i].y;
                m.z += rk * A[i].z; m.w += rk * A[i].w;
            }
#pragma unroll
        for (int i = 0; i < CH; ++i)
            A[i] = (k3 + i < K) ? W4[(k3 + i) * (DIM / 4)] : make_float4(0.f, 0.f, 0.f, 0.f);
#pragma unroll
        for (int i = 0; i < CH; ++i)
            if (k2 + i < K) {
                const float rk = r[k2 + i];
                m.x += rk * B[i].x; m.y += rk * B[i].y;
                m.z += rk * B[i].z; m.w += rk * B[i].w;
            }
    }
}

__device__ __forceinline__ float warp_sum(float s) {
#pragma unroll
    for (int o = 16; o; o >>= 1) s += __shfl_down_sync(0xffffffffu, s, o);
    return s;
}
__device__ __forceinline__ float4 relu4(float4 v) {
    return make_float4(fmaxf(v.x, 0.f), fmaxf(v.y, 0.f), fmaxf(v.z, 0.f), fmaxf(v.w, 0.f));
}
// Cooperative 8-warp L1 prefetch of one 64KB matrix (2 lines per lane).
__device__ __forceinline__ void prefetch_l1_slice(const char* base, int w, int c) {
    const char* p = base + (((w << 6) + c) << 7);
    asm volatile("prefetch.global.L1 [%0];" :: "l"(p));
    asm volatile("prefetch.global.L1 [%0];" :: "l"(p + (32 << 7)));
}

// ---------------------------------------------------------------------------
// Setup: one block per graph — structure (counts incl. effective wait counts,
// parents, path + per-node path index, onpath) and per-replay resets.
// ---------------------------------------------------------------------------
__global__ __launch_bounds__(128, 1) void k_setup(
        const int* __restrict__ graphs, const int* __restrict__ edges,
        const int* __restrict__ posp) {
    const int t = threadIdx.x;
    const int pos = posp[0];
    const int g = blockIdx.x;
    g_ccount[g][t] = 0;
    g_cdone[g][t]  = 0;
    g_onpath[g][t] = 0;
    g_pflag[g][t]  = 0;
    g_pathidx[g][t] = 0;
    for (int n = 0; n < NN; ++n) g_vacc[g][n][t] = 0.f;
    if (g == 0) g_edges_eff[t] = (t == pos) ? -1 : edges[t];
    __syncthreads();
    const int off = graphs[g * NN + t];
    const int par = (off == 0) ? -1 : (t + off);
    g_parent[g][t] = par;
    if (par >= 0) atomicAdd(&g_ccount[g][par], 1);
    if (t == 0) {
        int cur = pos, len = 0;
        while (len < NN) {
            g_path[g][len] = cur;
            g_onpath[g][cur] = 1;
            g_pathidx[g][cur] = len;
            ++len;
            const int o = graphs[g * NN + cur];
            if (o == 0) break;
            cur += o;
        }
        g_plen[g] = len;
    }
    __syncthreads();
    // effective wait count: path nodes (except pos) don't wait for the path
    // child — its contribution is the phase-2 matrix, not the vector part.
    g_ccount_eff[g][t] = g_ccount[g][t] - ((g_onpath[g][t] && t != pos) ? 1 : 0);
}

// ---------------------------------------------------------------------------
// Fused main kernel: 128 blocks x 256 threads, 1 block/SM -> all resident.
// Phase 0: block n computes base[n] = vecs[data[n]] @ dW + db (8-warp k-split
//   into shared sh_base).
// Phase 1: warp (block=n, g=w) owns tree task (n,g): wait ccount_eff child
//   signals (hot spin; path children excluded -> the pos->root spine is NOT
//   serialized), form v = base + vacc. Path node: (pos warp first writes
//   g_dscoreg[g]) store bvec, release its per-index flag pflag[g][idx]; NO
//   parent signal. Off-path: relu if internal, matvec, REDG into parent's
//   vacc, release parent counter.
// Phase 2 (overlapped): warp (g=b>>4, row e=(b&15)*8+w) walks the pos->root
//   chain; step s gated on pflag[g][s] (path nodes may complete out of order
//   now -> per-index flags, not a counter). Backoff polls.
// ---------------------------------------------------------------------------
__global__ __launch_bounds__(256, 1) void k_main(
        const int* __restrict__ data,  const float* __restrict__ vecs,
        const float* __restrict__ dW,  const float* __restrict__ db,
        const float* __restrict__ sdw, const float* __restrict__ sbias,
        const float* __restrict__ ew,  const float* __restrict__ ebias,
        const float* __restrict__ sew, const int* __restrict__ posp,
        float* __restrict__ out) {
    __shared__ __align__(16) float shv[304];
    __shared__ __align__(16) float part[8][DIM];
    __shared__ __align__(16) float sh_base[DIM];
    __shared__ __align__(16) float shr[8][DIM];
    const int t = threadIdx.x, w = t >> 5, c = t & 31;
    const int d0 = c * 4;
    const int b = blockIdx.x;

    // ================= phase 0: base[n] for this block's node ==============
    {
        const int n = b;
        const float* vr = vecs + (long long)data[n] * VEC;
        for (int i = t; i < 304; i += 256) shv[i] = (i < VEC) ? vr[i] : 0.f;
        __syncthreads();
        const int k0 = (w * VEC) >> 3, k1 = ((w + 1) * VEC) >> 3;   // 37/38 rows
        float4 acc = make_float4(0.f, 0.f, 0.f, 0.f);
#pragma unroll 8
        for (int k = k0; k < k1; ++k) {
            const float rv = shv[k];
            const float4 wv = *(const float4*)(dW + (long long)k * DIM + d0);
            acc.x += rv * wv.x; acc.y += rv * wv.y;
            acc.z += rv * wv.z; acc.w += rv * wv.w;
        }
        *(float4*)&part[w][d0] = acc;
        __syncthreads();
        if (w == 0) {
            float4 m = *(const float4*)(db + d0);
#pragma unroll
            for (int ww = 0; ww < 8; ++ww) {
                const float4 p = *(const float4*)&part[ww][d0];
                m.x += p.x; m.y += p.y; m.z += p.z; m.w += p.w;
            }
            *(float4*)&sh_base[d0] = m;
        }
        __syncthreads();
    }

    // ================= phase 1: vector task (n = block, g = warp) ==========
    {
        const int n = b;
        const int g = w;
        const int need   = g_ccount_eff[g][n];   // path child excluded
        const int par    = g_parent[g][n];
        const int onpath = g_onpath[g][n];
        const int eid    = g_edges_eff[n];
        const float* W = ew + (long long)eid * DIM * DIM;
        if (!onpath && need > 0) {
            // pull this task's weights toward L2 while waiting
            const char* wb = (const char*)W;
#pragma unroll
            for (int i = 0; i < 16; ++i)
                asm volatile("prefetch.global.L2 [%0];" :: "l"(wb + ((c + (i << 5)) << 7)));
        }
        if (need > 0) wait_ge(&g_cdone[g][n], need);
        float4 v = *(const float4*)&sh_base[d0];
        if (need > 0) {
            const float4 va = __ldcg((const float4*)&g_vacc[g][n][d0]);
            v.x += va.x; v.y += va.y; v.z += va.z; v.w += va.w;
        }
        if (onpath) {
            const int idx = g_pathidx[g][n];
            if (idx == 0) {                   // pos: per-graph d_score first
                const float4 bb = *(const float4*)&sh_base[d0];
                const float4 s4 = *(const float4*)(sdw + d0);
                const float s = warp_sum(bb.x * s4.x + bb.y * s4.y +
                                         bb.z * s4.z + bb.w * s4.w);
                if (c == 0) g_dscoreg[g] = sbias[0] + s;
            }
            *(float4*)&g_bvec[g][n][d0] = v;  // raw; relu by consumers
            __syncwarp();
            if (c == 0) red_release_add(&g_pflag[g][idx], 1);  // orders dscore+bvec
            // NO parent signal — the spine is not serialized in phase 1.
        } else {
            if (need > 0) v = relu4(v);       // relu only for internal nodes
            *(float4*)&shr[w][d0] = v;
            __syncwarp();
            float4 m = *(const float4*)(ebias + eid * DIM + d0);
            mv_stream<DIM, 16>((const float4*)(W + d0), shr[w], m);
            float* dst = &g_vacc[g][par][d0];
            atomicAdd(dst + 0, m.x); atomicAdd(dst + 1, m.y);
            atomicAdd(dst + 2, m.z); atomicAdd(dst + 3, m.w);
            __syncwarp();
            if (c == 0) red_release_add(&g_cdone[g][par], 1);
        }
        __syncwarp();
    }

    // ================= phase 2: matrix chain (g = b>>4, row e) =============
    {
        const int g = b >> 4;
        const int e = (b & 15) * 8 + w;
        {
            // warm L2 with this row's step-0 weights while waiting
            const char* wb = (const char*)(ew + (long long)e * DIM * DIM);
#pragma unroll
            for (int i = 0; i < 16; ++i)
                asm volatile("prefetch.global.L2 [%0];" :: "l"(wb + ((c + (i << 5)) << 7)));
        }
        const int plen = g_plen[g];            // from k_setup (prior launch)
        const int p0   = g_path[g][0];
        wait_ge_bk(&g_pflag[g][0], 1);         // v(pos) + dscore ready

        float4 r0 = __ldcg((const float4*)&g_bvec[g][p0][d0]);
        if (g_ccount[g][p0] > 0) r0 = relu4(r0);   // ORIGINAL child count
        *(float4*)&shr[w][d0] = r0;
        __syncwarp();

        // step 0: per-row weight matrix W[e]
        float4 m = *(const float4*)(ebias + e * DIM + d0);
        mv_stream<DIM, 16>((const float4*)(ew + (long long)e * DIM * DIM + d0), shr[w], m);

        // steps 1..plen-1: shared W per (graph, step), per-index flag gated
        for (int s = 1; s < plen; ++s) {
            const int a   = g_path[g][s];
            const int eid = g_edges_eff[a];
            prefetch_l1_slice((const char*)(ew + (long long)eid * DIM * DIM), w, c);
            wait_ge_bk(&g_pflag[g][s], 1);
            const float4 bv = __ldcg((const float4*)&g_bvec[g][a][d0]);
            const float4 r = make_float4(fmaxf(bv.x + m.x, 0.f), fmaxf(bv.y + m.y, 0.f),
                                         fmaxf(bv.z + m.z, 0.f), fmaxf(bv.w + m.w, 0.f));
            __syncwarp();                      // all lanes done reading prior shr
            *(float4*)&shr[w][d0] = r;
            __syncwarp();
            m = *(const float4*)(ebias + eid * DIM + d0);
            mv_stream<DIM, 16>((const float4*)(ew + (long long)eid * DIM * DIM + d0), shr[w], m);
        }

        const float4 s4 = *(const float4*)(sew + d0);
        const float s = warp_sum(m.x * s4.x + m.y * s4.y + m.z * s4.z + m.w * s4.w);
        if (c == 0) out[g * NE + e] = __ldcg(&g_dscoreg[g]) + s;
    }
}

extern "C" void kernel_launch(void* const* d_in, const int* in_sizes, int n_in,
                              void* d_out, int out_size) {
    const int*   data   = (const int*)d_in[0];
    // d_in[1] = types (unused: single data_type)
    const int*   graphs = (const int*)d_in[2];
    const int*   edges  = (const int*)d_in[3];
    const int*   posp   = (const int*)d_in[4];
    const float* vecs   = (const float*)d_in[5];
    const float* dW     = (const float*)d_in[6];
    const float* db     = (const float*)d_in[7];
    const float* ew     = (const float*)d_in[8];
    const float* ebias  = (const float*)d_in[9];
    const float* sew    = (const float*)d_in[10];
    const float* sdw    = (const float*)d_in[11];
    const float* sbias  = (const float*)d_in[12];
    float* out = (float*)d_out;

    k_setup<<<NG, 128>>>(graphs, edges, posp);
    k_main<<<NN, 256>>>(data, vecs, dW, db, sdw, sbias,
                        ew, ebias, sew, posp, out);
}

// round 16
// speedup vs baseline: 1.4298x; 1.4298x over previous
#include <cuda_runtime.h>

#define NG  8     // graphs
#define NN  128   // nodes
#define DIM 128   // embedding dim
#define NE  128   // edge types
#define VEC 300   // word-vec dim

// ---- scratch (device globals; no allocations allowed) ----
__device__ __align__(16) float g_base[NN][DIM];
__device__ __align__(16) float g_vacc[NG][NN][DIM];
__device__ __align__(16) float g_bvec[NG][NN][DIM];
__device__ int   g_parent[NG][NN];
__device__ int   g_ccount[NG][NN];
__device__ int   g_cdone[NG][NN];
__device__ int   g_onpath[NG][NN];
__device__ int   g_path[NG][NN];
__device__ int   g_plen[NG];
__device__ int   g_edges_eff[NN];
__device__ int   g_rootdone[NG];
__device__ float g_dscore;

// ---- acquire/release primitives ----
__device__ __forceinline__ int ld_acquire(const int* p) {
    int v;
    asm volatile("ld.acquire.gpu.global.u32 %0, [%1];" : "=r"(v) : "l"(p) : "memory");
    return v;
}
__device__ __forceinline__ void red_release_add(int* p, int v) {
    asm volatile("red.release.gpu.global.add.u32 [%0], %1;" :: "l"(p), "r"(v) : "memory");
}
// ALL lanes spin (each lane carries its own acquire edge; same-address load
// broadcasts, so a poll costs one wavefront). Formal HB to every lane.
__device__ __forceinline__ void wait_ge(const int* p, int need) {
    while (ld_acquire(p) < need) { }
    __syncwarp();
}

// ---------------------------------------------------------------------------
// Streaming matvec: thread owns 4 consecutive output dims (d0 = 4*lane).
// W4 points at W[0][d0] (row stride DIM floats). Double-buffered register
// chunks -> 2*CH LDG.128 in flight per thread (needs launch_bounds(...,1)).
// ---------------------------------------------------------------------------
template<int K, int CH>
__device__ __forceinline__ void mv_stream(const float4* __restrict__ W4,
                                          const float* __restrict__ r,
                                          float4& m) {
    constexpr int STEP = 2 * CH;
    constexpr int NCH  = (K + STEP - 1) / STEP;
    float4 A[CH], B[CH];
#pragma unroll
    for (int i = 0; i < CH; ++i)
        A[i] = (i < K) ? W4[i * (DIM / 4)] : make_float4(0.f, 0.f, 0.f, 0.f);
#pragma unroll
    for (int o = 0; o < NCH; ++o) {
        const int kb = o * STEP, k2 = kb + CH, k3 = kb + STEP;
#pragma unroll
        for (int i = 0; i < CH; ++i)
            B[i] = (k2 + i < K) ? W4[(k2 + i) * (DIM / 4)] : make_float4(0.f, 0.f, 0.f, 0.f);
#pragma unroll
        for (int i = 0; i < CH; ++i)
            if (kb + i < K) {
                const float rk = r[kb + i];
                m.x += rk * A[i].x; m.y += rk * A[i].y;
                m.z += rk * A[i].z; m.w += rk * A[i].w;
            }
#pragma unroll
        for (int i = 0; i < CH; ++i)
            A[i] = (k3 + i < K) ? W4[(k3 + i) * (DIM / 4)] : make_float4(0.f, 0.f, 0.f, 0.f);
#pragma unroll
        for (int i = 0; i < CH; ++i)
            if (k2 + i < K) {
                const float rk = r[k2 + i];
                m.x += rk * B[i].x; m.y += rk * B[i].y;
                m.z += rk * B[i].z; m.w += rk * B[i].w;
            }
    }
}

__device__ __forceinline__ float warp_sum(float s) {
#pragma unroll
    for (int o = 16; o; o >>= 1) s += __shfl_down_sync(0xffffffffu, s, o);
    return s;
}

__device__ __forceinline__ float4 relu4(float4 v) {
    return make_float4(fmaxf(v.x, 0.f), fmaxf(v.y, 0.f), fmaxf(v.z, 0.f), fmaxf(v.w, 0.f));
}

// ---------------------------------------------------------------------------
// Setup. Blocks 0..7: tree structure + scratch reset for one graph each.
// Blocks 8..39: warp-per-node base embeddings base[n] = vecs[data[n]]@dW + db
// (32 blocks x 4 warps = 128 nodes, one warp per node, full-K stream).
// The warp owning node==pos also computes d_score = sbias + base[pos].sdw.
// ---------------------------------------------------------------------------
__global__ __launch_bounds__(128, 1) void k_setup(
        const int* __restrict__ graphs, const int* __restrict__ edges,
        const int* __restrict__ posp,   const int* __restrict__ data,
        const float* __restrict__ vecs, const float* __restrict__ dW,
        const float* __restrict__ db,   const float* __restrict__ sdw,
        const float* __restrict__ sbias) {
    const int t = threadIdx.x;
    const int pos = posp[0];
    if (blockIdx.x < NG) {
        const int g = blockIdx.x;
        g_ccount[g][t] = 0;
        g_cdone[g][t]  = 0;
        g_onpath[g][t] = 0;
        for (int n = 0; n < NN; ++n) g_vacc[g][n][t] = 0.f;
        if (g == 0) g_edges_eff[t] = (t == pos) ? -1 : edges[t];
        if (t == 0) g_rootdone[g] = 0;
        __syncthreads();
        const int off = graphs[g * NN + t];
        const int par = (off == 0) ? -1 : (t + off);
        g_parent[g][t] = par;
        if (par >= 0) atomicAdd(&g_ccount[g][par], 1);
        if (t == 0) {
            int cur = pos, len = 0;
            while (len < NN) {
                g_path[g][len++] = cur;
                g_onpath[g][cur] = 1;
                const int o = graphs[g * NN + cur];
                if (o == 0) break;
                cur += o;
            }
            g_plen[g] = len;
        }
    } else {
        __shared__ __align__(16) float shv[4][304];
        const int w = t >> 5, c = t & 31;
        const int n = (blockIdx.x - NG) * 4 + w;      // 32 blocks * 4 warps = 128 nodes
        const float* v = vecs + (long long)data[n] * VEC;
        for (int i = c; i < 304; i += 32) shv[w][i] = (i < VEC) ? v[i] : 0.f;
        __syncwarp();
        const int d0 = c * 4;
        float4 m = *(const float4*)(db + d0);
        mv_stream<VEC, 8>((const float4*)(dW + d0), shv[w], m);
        *(float4*)&g_base[n][d0] = m;
        if (n == pos) {
            const float4 s4 = *(const float4*)(sdw + d0);
            const float s = warp_sum(m.x * s4.x + m.y * s4.y + m.z * s4.z + m.w * s4.w);
            if (c == 0) g_dscore = sbias[0] + s;
        }
    }
}

// ---------------------------------------------------------------------------
// Fused main kernel: 128 blocks x 8 warps = 1024 resident warps (1 block/SM,
// 128 <= 148 SMs -> all producers co-resident; spins cannot deadlock).
// Phase 1 (vector): warp (block=n, warp=g) owns tree task (n,g). Wait for the
//   child done-counter (all-lane acquire), finalize the node vector, then
//   either store it (pos->root path node) or matvec-transform and atomic-add
//   into the parent accumulator; signal with release-add.
// Phase 2 (matrix): warp (g=block>>4, row e=(block&15)*8+w) waits on the
//   graph's rootdone flag, then walks the pos->root chain of matvecs for its
//   edge row and emits the score. Early graphs overlap late vector work.
// ---------------------------------------------------------------------------
__global__ __launch_bounds__(256, 1) void k_main(const float* __restrict__ ew,
                                                 const float* __restrict__ ebias,
                                                 const float* __restrict__ sew,
                                                 float* __restrict__ out) {
    __shared__ __align__(16) float shr[8][DIM];
    const int t = threadIdx.x;
    const int w = t >> 5, c = t & 31;
    const int d0 = c * 4;

    // ---------------- phase 1: vector task (n = block, g = warp) ----------
    {
        const int n = blockIdx.x;
        const int g = w;
        const int need   = g_ccount[g][n];
        const int par    = g_parent[g][n];
        const int onpath = g_onpath[g][n];
        const int eid    = g_edges_eff[n];
        const float* W = ew + (long long)eid * DIM * DIM;
        if (!onpath && need > 0) {
            // pull this task's weights toward L2 while waiting
            const char* wb = (const char*)W;
#pragma unroll
            for (int i = 0; i < 16; ++i)
                asm volatile("prefetch.global.L2 [%0];" :: "l"(wb + ((c + (i << 5)) << 7)));
        }
        if (need > 0) wait_ge(&g_cdone[g][n], need);
        float4 v = *(const float4*)&g_base[n][d0];
        if (need > 0) {
            const float4 va = __ldcg((const float4*)&g_vacc[g][n][d0]);
            v.x += va.x; v.y += va.y; v.z += va.z; v.w += va.w;
        }
        if (onpath) {
            *(float4*)&g_bvec[g][n][d0] = v;
            __syncwarp();
            if (c == 0) {
                if (par >= 0) red_release_add(&g_cdone[g][par], 1);
                else          red_release_add(&g_rootdone[g], 1);
            }
        } else {
            if (need > 0) v = relu4(v);       // relu only for internal nodes
            *(float4*)&shr[w][d0] = v;
            __syncwarp();
            float4 m = *(const float4*)(ebias + eid * DIM + d0);
            mv_stream<DIM, 16>((const float4*)(W + d0), shr[w], m);
            float* dst = &g_vacc[g][par][d0];
            atomicAdd(dst + 0, m.x); atomicAdd(dst + 1, m.y);
            atomicAdd(dst + 2, m.z); atomicAdd(dst + 3, m.w);
            __syncwarp();
            if (c == 0) red_release_add(&g_cdone[g][par], 1);
        }
        __syncwarp();
    }

    // ---------------- phase 2: matrix chain (g = block>>4, row e) ----------
    {
        const int g = blockIdx.x >> 4;
        const int e = (blockIdx.x & 15) * 8 + w;
        {
            // warm L2 with this row's step-0 weights while waiting
            const char* wb = (const char*)(ew + (long long)e * DIM * DIM);
#pragma unroll
            for (int i = 0; i < 16; ++i)
                asm volatile("prefetch.global.L2 [%0];" :: "l"(wb + ((c + (i << 5)) << 7)));
        }
        wait_ge(&g_rootdone[g], 1);

        const int plen = g_plen[g];
        const int p0   = g_path[g][0];

        float4 r0 = __ldcg((const float4*)&g_bvec[g][p0][d0]);
        if (g_ccount[g][p0] > 0) r0 = relu4(r0);
        *(float4*)&shr[w][d0] = r0;
        __syncwarp();

        // step 0: per-row weight matrix W[e]
        float4 m = *(const float4*)(ebias + e * DIM + d0);
        mv_stream<DIM, 16>((const float4*)(ew + (long long)e * DIM * DIM + d0), shr[w], m);

        // steps 1..plen-1: shared weight matrix per (graph, step)
        for (int s = 1; s < plen; ++s) {
            const int a = g_path[g][s];
            const float4 bv = __ldcg((const float4*)&g_bvec[g][a][d0]);
            const float4 r = make_float4(fmaxf(bv.x + m.x, 0.f), fmaxf(bv.y + m.y, 0.f),
                                         fmaxf(bv.z + m.z, 0.f), fmaxf(bv.w + m.w, 0.f));
            __syncwarp();                      // all lanes done reading prior shr
            *(float4*)&shr[w][d0] = r;
            __syncwarp();
            const int eid = g_edges_eff[a];
            m = *(const float4*)(ebias + eid * DIM + d0);
            mv_stream<DIM, 16>((const float4*)(ew + (long long)eid * DIM * DIM + d0), shr[w], m);
        }

        const float4 s4 = *(const float4*)(sew + d0);
        const float s = warp_sum(m.x * s4.x + m.y * s4.y + m.z * s4.z + m.w * s4.w);
        if (c == 0) out[g * NE + e] = g_dscore + s;
    }
}

extern "C" void kernel_launch(void* const* d_in, const int* in_sizes, int n_in,
                              void* d_out, int out_size) {
    const int*   data   = (const int*)d_in[0];
    // d_in[1] = types (unused: single data_type)
    const int*   graphs = (const int*)d_in[2];
    const int*   edges  = (const int*)d_in[3];
    const int*   posp   = (const int*)d_in[4];
    const float* vecs   = (const float*)d_in[5];
    const float* dW     = (const float*)d_in[6];
    const float* db     = (const float*)d_in[7];
    const float* ew     = (const float*)d_in[8];
    const float* ebias  = (const float*)d_in[9];
    const float* sew    = (const float*)d_in[10];
    const float* sdw    = (const float*)d_in[11];
    const float* sbias  = (const float*)d_in[12];
    float* out = (float*)d_out;

    k_setup<<<NG + 32, 128>>>(graphs, edges, posp, data, vecs, dW, db, sdw, sbias);
    k_main<<<128, 256>>>(ew, ebias, sew, out);
}